// round 13
// baseline (speedup 1.0000x reference)
#include <cuda_runtime.h>
#include <cstdint>
#include <math.h>

// ---------------------------------------------------------------- constants
#define NB   32
#define NS   2048
#define ND   768
#define NE   8
#define NH   256
#define TOK  (NB*NS)          // 65536
#define G3   (3*NH)           // 768

// output layout (float32, concatenated flattened tuple)
#define OUT_EW   0
#define OUT_IDX  (TOK*4)                // 262144
#define OUT_RW   (TOK*8)                // 524288
#define OUT_NH   (OUT_RW + TOK*8)       // 1048576
#define OUT_C    (OUT_NH + NB*NH)       // 1056768
#define OUT_LB   (OUT_C + TOK)          // 1122304
#define OUT_CR   (OUT_LB + 1)           // 1122305

// ---------------------------------------------------------------- scratch
__device__ float  g_gi[(size_t)TOK * G3];     // [B*S, 768]
__device__ float  g_g [(size_t)TOK * NH];     // [B*S, 256]
__device__ float  g_feats[(size_t)TOK * 256]; // heads gemm out
__device__ float  g_Wcomb[256 * 256];
__device__ float  g_bcomb[256];
__device__ double g_acc[9];                   // 8 usage sums + complexity^2 sum

// ---------------------------------------------------------------- helpers
__device__ __forceinline__ unsigned long long dup2f(float x) {
    unsigned long long r;
    asm("mov.b64 %0, {%1, %1};" : "=l"(r) : "f"(x));
    return r;
}
__device__ __forceinline__ void fma2(unsigned long long& acc,
                                     unsigned long long a, unsigned long long b) {
    asm("fma.rn.f32x2 %0, %1, %2, %0;" : "+l"(acc) : "l"(a), "l"(b));
}
__device__ __forceinline__ float2 unpack2(unsigned long long v) {
    float2 f;
    asm("mov.b64 {%0, %1}, %2;" : "=f"(f.x), "=f"(f.y) : "l"(v));
    return f;
}
__device__ __forceinline__ uint32_t smem_u32(const void* p) {
    uint32_t a;
    asm("{ .reg .u64 t; cvta.to.shared.u64 t, %1; cvt.u32.u64 %0, t; }"
        : "=r"(a) : "l"(p));
    return a;
}
__device__ __forceinline__ void st_cluster_f32(uint32_t saddr, uint32_t rank, float v) {
    uint32_t r;
    asm volatile("mapa.shared::cluster.u32 %0, %1, %2;" : "=r"(r) : "r"(saddr), "r"(rank));
    asm volatile("st.shared::cluster.f32 [%0], %1;" :: "r"(r), "f"(v) : "memory");
}
__device__ __forceinline__ void cluster_arrive_() {
    asm volatile("barrier.cluster.arrive.aligned;" ::: "memory");
}
__device__ __forceinline__ void cluster_wait_() {
    asm volatile("barrier.cluster.wait.aligned;" ::: "memory");
}
__device__ __forceinline__ void cluster_sync_() {
    cluster_arrive_(); cluster_wait_();
}

// ============================================================== SGEMM (NT)
// C[m][n] = sum_k A[m][k]*B[n][k] + bias[n]
// BM=BN=128, BK=16, 256 threads, 8x8 per thread via f32x2.
// DOUBLE-BUFFERED smem: one __syncthreads per tile (was two).
__global__ __launch_bounds__(256, 2)
void sgemm_nt(const float* __restrict__ A, int lda,
              const float* __restrict__ B, int ldb,
              const float* __restrict__ bias,
              float* __restrict__ C, int ldc, int K)
{
    __shared__ float As[2][16 * 128];
    __shared__ float Bs[2][16 * 128];

    const int tid = threadIdx.x;
    const int tx  = tid & 15, ty = tid >> 4;
    const int tx4 = tx * 4,  ty4 = ty * 4;
    const size_t bm = (size_t)blockIdx.y * 128;
    const size_t bn = (size_t)blockIdx.x * 128;

    const int r0 = tid >> 2;          // 0..63
    const int r1 = r0 + 64;
    const int c4 = (tid & 3) * 4;     // 0,4,8,12

    const float* Ag0 = A + (bm + r0) * (size_t)lda + c4;
    const float* Ag1 = A + (bm + r1) * (size_t)lda + c4;
    const float* Bg0 = B + (bn + r0) * (size_t)ldb + c4;
    const float* Bg1 = B + (bn + r1) * (size_t)ldb + c4;

    unsigned long long acc[8][4];
#pragma unroll
    for (int i = 0; i < 8; i++)
#pragma unroll
        for (int jp = 0; jp < 4; jp++) acc[i][jp] = 0ull;

    // chunk 0 -> buffer 0
    float4 pa0 = *(const float4*)Ag0;
    float4 pa1 = *(const float4*)Ag1;
    float4 pb0 = *(const float4*)Bg0;
    float4 pb1 = *(const float4*)Bg1;
#pragma unroll
    for (int jj = 0; jj < 4; jj++) {
        As[0][(c4 + jj) * 128 + r0] = ((const float*)&pa0)[jj];
        As[0][(c4 + jj) * 128 + r1] = ((const float*)&pa1)[jj];
        Bs[0][(c4 + jj) * 128 + r0] = ((const float*)&pb0)[jj];
        Bs[0][(c4 + jj) * 128 + r1] = ((const float*)&pb1)[jj];
    }
    __syncthreads();

    const int nk = K >> 4;
    int p = 0;
    for (int kt = 0; kt < nk; kt++) {
        const bool has_next = (kt + 1 < nk);
        if (has_next) {
            const int off = (kt + 1) * 16;
            pa0 = *(const float4*)(Ag0 + off);
            pa1 = *(const float4*)(Ag1 + off);
            pb0 = *(const float4*)(Bg0 + off);
            pb1 = *(const float4*)(Bg1 + off);
        }

        const float* asb = As[p];
        const float* bsb = Bs[p];
#pragma unroll
        for (int k = 0; k < 16; k++) {
            const float* asr = asb + k * 128;
            float4 a0 = *(const float4*)(asr + ty4);
            float4 a1 = *(const float4*)(asr + 64 + ty4);
            const ulonglong2* bsr = (const ulonglong2*)(bsb + k * 128);
            ulonglong2 b0 = bsr[tx];
            ulonglong2 b1 = bsr[16 + tx];
            float am[8] = {a0.x, a0.y, a0.z, a0.w, a1.x, a1.y, a1.z, a1.w};
#pragma unroll
            for (int i = 0; i < 8; i++) {
                unsigned long long ad = dup2f(am[i]);
                fma2(acc[i][0], ad, b0.x);
                fma2(acc[i][1], ad, b0.y);
                fma2(acc[i][2], ad, b1.x);
                fma2(acc[i][3], ad, b1.y);
            }
        }

        if (has_next) {
            float* ad_ = As[p ^ 1];
            float* bd_ = Bs[p ^ 1];
#pragma unroll
            for (int jj = 0; jj < 4; jj++) {
                ad_[(c4 + jj) * 128 + r0] = ((const float*)&pa0)[jj];
                ad_[(c4 + jj) * 128 + r1] = ((const float*)&pa1)[jj];
                bd_[(c4 + jj) * 128 + r0] = ((const float*)&pb0)[jj];
                bd_[(c4 + jj) * 128 + r1] = ((const float*)&pb1)[jj];
            }
        }
        __syncthreads();   // single barrier per tile
        p ^= 1;
    }

    float4 bb0 = *(const float4*)(bias + bn + tx4);
    float4 bb1 = *(const float4*)(bias + bn + 64 + tx4);

#pragma unroll
    for (int i = 0; i < 8; i++) {
        size_t m = bm + (size_t)((i < 4) ? (ty4 + i) : (64 + ty4 + (i - 4)));
        float2 p0 = unpack2(acc[i][0]);
        float2 p1 = unpack2(acc[i][1]);
        float2 p2 = unpack2(acc[i][2]);
        float2 p3 = unpack2(acc[i][3]);
        float4 o0 = make_float4(p0.x + bb0.x, p0.y + bb0.y, p1.x + bb0.z, p1.y + bb0.w);
        float4 o1 = make_float4(p2.x + bb1.x, p2.y + bb1.y, p3.x + bb1.z, p3.y + bb1.w);
        *(float4*)&C[m * (size_t)ldc + bn + tx4]      = o0;
        *(float4*)&C[m * (size_t)ldc + bn + 64 + tx4] = o1;
    }
}

// ============================================================== GRU scan
// TWO batches per 4-CTA cluster (grid 4 x 16): the register-resident W_hh
// slice is reused for both sequences, so the per-step overhead
// (cluster.sync, DSMEM stores, gate chain, barrier drain) is amortized
// over two batch-steps while gemv issue work scales.
#define GRU_THREADS 384

__global__ void __cluster_dims__(4, 1, 1) __launch_bounds__(GRU_THREADS, 1)
gru_kernel(const float* __restrict__ W_hh, const float* __restrict__ b_hh,
           float* __restrict__ out_hidden)
{
    __shared__ float hb[2][2][256];     // [batch][pingpong][unit]
    __shared__ float ps[2][GRU_THREADS];

    const int tid  = threadIdx.x;
    const int rank = blockIdx.x;              // 0..3
    const int b0   = blockIdx.y * 2;          // batches 2i, 2i+1
    const int b1   = b0 + 1;
    const int half = (tid >= 192) ? 1 : 0;    // K-half (warp-uniform)
    const int r    = tid - half * 192;        // row 0..191 (= g*64 + j)
    const int g    = r >> 6;
    const int j    = r & 63;
    const int u    = rank * 64 + tid;         // unit id (valid only tid<64)

    // W_hh row slice in registers: 128 floats = 32 x 16B (shared across batches)
    ulonglong2 w[32];
    {
        const ulonglong2* src = (const ulonglong2*)
            (W_hh + ((size_t)(g * 256 + rank * 64 + j)) * 256 + half * 128);
#pragma unroll
        for (int i = 0; i < 32; i++) w[i] = src[i];
    }

    if (tid < 256) {
        hb[0][0][tid] = 0.f; hb[0][1][tid] = 0.f;
        hb[1][0][tid] = 0.f; hb[1][1][tid] = 0.f;
    }

    float bhr = 0.f, bhz = 0.f, bhn = 0.f;
    if (tid < 64) {
        bhr = b_hh[u]; bhz = b_hh[256 + u]; bhn = b_hh[512 + u];
    }
    __syncthreads();
    cluster_sync_();

    const float* gia = g_gi + (size_t)b0 * NS * G3;
    const float* gib = g_gi + (size_t)b1 * NS * G3;
    float*       goa = g_g  + (size_t)b0 * NS * NH;
    float*       gob = g_g  + (size_t)b1 * NS * NH;
    const uint32_t hb_u32 = smem_u32(&hb[0][0][0]);

    // gi software pipeline (both batches)
    float ar = 0.f, az = 0.f, an = 0.f, br_ = 0.f, bz = 0.f, bn_ = 0.f;
    if (tid < 64) {
        ar  = gia[u]; az = gia[256 + u]; an  = gia[512 + u];
        br_ = gib[u]; bz = gib[256 + u]; bn_ = gib[512 + u];
    }

    int p = 0;
#pragma unroll 1
    for (int t = 0; t < NS; t++) {
        // prefetch gi(t+1) for both batches
        float nar = 0.f, naz = 0.f, nan_ = 0.f, nbr = 0.f, nbz = 0.f, nbn = 0.f;
        if (tid < 64 && t + 1 < NS) {
            const float* ga = gia + (size_t)(t + 1) * G3;
            const float* gb = gib + (size_t)(t + 1) * G3;
            nar = ga[u]; naz = ga[256 + u]; nan_ = ga[512 + u];
            nbr = gb[u]; nbz = gb[256 + u]; nbn  = gb[512 + u];
        }

        // gemv batch 0 (accumulators reused by batch 1 — serialized lifetimes)
        {
            const ulonglong2* hv = (const ulonglong2*)(&hb[0][p][half * 128]);
            unsigned long long a0 = 0ull, a1 = 0ull, a2 = 0ull, a3 = 0ull;
#pragma unroll
            for (int i = 0; i < 32; i += 2) {
                ulonglong2 h0 = hv[i], h1 = hv[i + 1];
                fma2(a0, w[i].x,     h0.x);
                fma2(a1, w[i].y,     h0.y);
                fma2(a2, w[i + 1].x, h1.x);
                fma2(a3, w[i + 1].y, h1.y);
            }
            float2 f0 = unpack2(a0), f1 = unpack2(a1), f2 = unpack2(a2), f3 = unpack2(a3);
            ps[0][tid] = ((f0.x + f0.y) + (f1.x + f1.y)) + ((f2.x + f2.y) + (f3.x + f3.y));
        }
        // gemv batch 1
        {
            const ulonglong2* hv = (const ulonglong2*)(&hb[1][p][half * 128]);
            unsigned long long a0 = 0ull, a1 = 0ull, a2 = 0ull, a3 = 0ull;
#pragma unroll
            for (int i = 0; i < 32; i += 2) {
                ulonglong2 h0 = hv[i], h1 = hv[i + 1];
                fma2(a0, w[i].x,     h0.x);
                fma2(a1, w[i].y,     h0.y);
                fma2(a2, w[i + 1].x, h1.x);
                fma2(a3, w[i + 1].y, h1.y);
            }
            float2 f0 = unpack2(a0), f1 = unpack2(a1), f2 = unpack2(a2), f3 = unpack2(a3);
            ps[1][tid] = ((f0.x + f0.y) + (f1.x + f1.y)) + ((f2.x + f2.y) + (f3.x + f3.y));
        }
        __syncthreads();   // the only intra-CTA barrier per step

        float h0n = 0.f, h1n = 0.f;
        if (tid < 64) {
            float hold0 = hb[0][p][u];
            float hold1 = hb[1][p][u];
            float hr0 = ps[0][tid]       + ps[0][192 + tid];
            float hz0 = ps[0][64 + tid]  + ps[0][256 + tid];
            float hn0 = ps[0][128 + tid] + ps[0][320 + tid];
            float hr1 = ps[1][tid]       + ps[1][192 + tid];
            float hz1 = ps[1][64 + tid]  + ps[1][256 + tid];
            float hn1 = ps[1][128 + tid] + ps[1][320 + tid];
            // two independent gate chains -> ILP hides exp/tanh latency
            float rr0 = 1.f / (1.f + expf(-(ar  + bhr + hr0)));
            float rr1 = 1.f / (1.f + expf(-(br_ + bhr + hr1)));
            float zz0 = 1.f / (1.f + expf(-(az  + bhz + hz0)));
            float zz1 = 1.f / (1.f + expf(-(bz  + bhz + hz1)));
            float n20 = tanhf(an  + bhn + rr0 * hn0);
            float n21 = tanhf(bn_ + bhn + rr1 * hn1);
            h0n = (1.f - zz0) * n20 + zz0 * hold0;
            h1n = (1.f - zz1) * n21 + zz1 * hold1;

            uint32_t d0 = hb_u32 + (uint32_t)((((p ^ 1) * 256) + u) * 4);
            uint32_t d1 = d0 + 2048;   // hb[1] is 512 floats after hb[0]
#pragma unroll
            for (int c = 0; c < 4; c++) {
                st_cluster_f32(d0, (uint32_t)c, h0n);
                st_cluster_f32(d1, (uint32_t)c, h1n);
            }
        }
        cluster_arrive_();   // release covers the remote stores
        if (tid < 64) {
            goa[(size_t)t * NH + u] = h0n;
            gob[(size_t)t * NH + u] = h1n;
            if (t == NS - 1) {
                out_hidden[b0 * NH + u] = h0n;
                out_hidden[b1 * NH + u] = h1n;
            }
        }
        cluster_wait_();
        p ^= 1;
        ar = nar; az = naz; an = nan_;
        br_ = nbr; bz = nbz; bn_ = nbn;
    }
    cluster_sync_();
}

// ============================================================== prep
__global__ void prep_kernel(const float* __restrict__ Wc1, const float* __restrict__ bc1,
                            const float* __restrict__ Wr,  const float* __restrict__ br,
                            const float* __restrict__ Wk1, const float* __restrict__ bk1)
{
    int r = blockIdx.x, c = threadIdx.x;
    float v = 0.f, bv = 0.f;
    if (r < 128)       { v = Wc1[r * 256 + c];         bv = bc1[r];       }
    else if (r < 136)  { v = Wr [(r - 128) * 256 + c]; bv = br [r - 128]; }
    else if (r < 200)  { v = Wk1[(r - 136) * 256 + c]; bv = bk1[r - 136]; }
    g_Wcomb[r * 256 + c] = v;
    if (c == 0) g_bcomb[r] = bv;
    if (r == 0 && c < 9) g_acc[c] = 0.0;
}

// ============================================================== router
__global__ __launch_bounds__(256)
void router_kernel(const float* __restrict__ Wc2, const float* __restrict__ bc2,
                   const float* __restrict__ Wk2, const float* __restrict__ bk2,
                   float* __restrict__ out)
{
    __shared__ double sacc[9];
    const int tid = threadIdx.x;
    if (tid < 9) sacc[tid] = 0.0;
    __syncthreads();

    const int warp = tid >> 5, lane = tid & 31;
    const int i = blockIdx.x * 8 + warp;
    const float* row = g_feats + (size_t)i * 256;

    float4 f = *(const float4*)(row + lane * 4);
    float4 w = *(const float4*)(Wc2 + lane * 4);
    float s = fmaxf(f.x, 0.f) * w.x + fmaxf(f.y, 0.f) * w.y +
              fmaxf(f.z, 0.f) * w.z + fmaxf(f.w, 0.f) * w.w;
    float2 f2 = *(const float2*)(row + 136 + lane * 2);
    float2 w2 = *(const float2*)(Wk2 + lane * 2);
    float s2 = fmaxf(f2.x, 0.f) * w2.x + fmaxf(f2.y, 0.f) * w2.y;
#pragma unroll
    for (int o = 16; o > 0; o >>= 1) {
        s  += __shfl_xor_sync(0xffffffffu, s,  o);
        s2 += __shfl_xor_sync(0xffffffffu, s2, o);
    }

    if (lane == 0) {
        float comp = 1.f / (1.f + expf(-(s + bc2[0])));
        float tsc  = 1.f / (1.f + expf(-(s2 + bk2[0])));

        float lg[NE];
        float mx = -1e30f;
#pragma unroll
        for (int e = 0; e < NE; e++) { lg[e] = row[128 + e]; mx = fmaxf(mx, lg[e]); }
        float sum = 0.f;
#pragma unroll
        for (int e = 0; e < NE; e++) { lg[e] = expf(lg[e] - mx); sum += lg[e]; }
        float inv = 1.f / sum;
        float rw[NE];
#pragma unroll
        for (int e = 0; e < NE; e++) {
            rw[e] = lg[e] * inv;
            out[OUT_RW + (size_t)i * NE + e] = rw[e];
        }

        int   idx[4];
        float tv[4];
        bool  used[NE] = {false, false, false, false, false, false, false, false};
#pragma unroll
        for (int s4 = 0; s4 < 4; s4++) {
            int best = 0; float bv = -1e30f;
#pragma unroll
            for (int e = 0; e < NE; e++)
                if (!used[e] && rw[e] > bv) { bv = rw[e]; best = e; }
            used[best] = true; tv[s4] = bv; idx[s4] = best;
        }

        float combined = 0.7f * comp + 0.3f * tsc;
        int kk = (int)rintf(1.f + combined * 3.f);
        if (kk < 1) kk = 1; if (kk > 4) kk = 4;

        float ms = 0.f, mw[4];
#pragma unroll
        for (int s4 = 0; s4 < 4; s4++) { mw[s4] = (s4 < kk) ? tv[s4] : 0.f; ms += mw[s4]; }
        if (!(ms > 0.f)) ms = 1.f;
        float im = 1.f / ms;
#pragma unroll
        for (int s4 = 0; s4 < 4; s4++) {
            out[OUT_EW  + (size_t)i * 4 + s4] = mw[s4] * im;
            out[OUT_IDX + (size_t)i * 4 + s4] = (float)idx[s4];
        }
        out[OUT_C + i] = comp;

#pragma unroll
        for (int e = 0; e < NE; e++) atomicAdd(&sacc[e], (double)rw[e]);
        atomicAdd(&sacc[8], (double)comp * (double)comp);
    }
    __syncthreads();
    if (tid < 9) atomicAdd(&g_acc[tid], sacc[tid]);
}

// ============================================================== finalize
__global__ void finalize_kernel(float* __restrict__ out)
{
    double s = 0.0;
#pragma unroll
    for (int e = 0; e < NE; e++) {
        double u = g_acc[e] / (double)TOK - 1.0 / (double)NE;
        s += u * u;
    }
    out[OUT_LB] = (float)(s / (double)NE * 0.01);
    out[OUT_CR] = (float)(g_acc[8] / (double)TOK * 0.001);
}

// ============================================================== launch
extern "C" void kernel_launch(void* const* d_in, const int* in_sizes, int n_in,
                              void* d_out, int out_size)
{
    (void)in_sizes; (void)n_in; (void)out_size;
    const float* x    = (const float*)d_in[0];
    // d_in[1] = layer_idx (unused)
    const float* W_ih = (const float*)d_in[2];   // [768, 776]
    const float* W_hh = (const float*)d_in[3];   // [768, 256]
    const float* b_ih = (const float*)d_in[4];
    const float* b_hh = (const float*)d_in[5];
    const float* Wc1  = (const float*)d_in[6];
    const float* bc1  = (const float*)d_in[7];
    const float* Wc2  = (const float*)d_in[8];
    const float* bc2  = (const float*)d_in[9];
    const float* Wr   = (const float*)d_in[10];
    const float* br   = (const float*)d_in[11];
    const float* Wk1  = (const float*)d_in[12];
    const float* bk1  = (const float*)d_in[13];
    const float* Wk2  = (const float*)d_in[14];
    const float* bk2  = (const float*)d_in[15];
    float* out = (float*)d_out;

    static float* p_gi = nullptr;
    static float* p_g = nullptr;
    static float* p_feats = nullptr;
    static float* p_wc = nullptr;
    static float* p_bc = nullptr;
    if (!p_gi) {
        cudaGetSymbolAddress((void**)&p_gi,    g_gi);
        cudaGetSymbolAddress((void**)&p_g,     g_g);
        cudaGetSymbolAddress((void**)&p_feats, g_feats);
        cudaGetSymbolAddress((void**)&p_wc,    g_Wcomb);
        cudaGetSymbolAddress((void**)&p_bc,    g_bcomb);
    }

    // 1. pack head weights + zero loss accumulators
    prep_kernel<<<256, 256>>>(Wc1, bc1, Wr, br, Wk1, bk1);

    // 2. gi = x @ W_ih[:, :768]^T + b_ih   (M=65536, N=768, K=768)
    sgemm_nt<<<dim3(G3 / 128, TOK / 128), 256>>>(x, ND, W_ih, ND + NE, b_ih,
                                                 p_gi, G3, ND);

    // 3. GRU scan — 2 batches per 4-CTA cluster (grid 4 x 16)
    gru_kernel<<<dim3(4, NB / 2), GRU_THREADS>>>(W_hh, b_hh, out + OUT_NH);

    // 4. heads: feats = g @ Wcomb^T + bcomb   (M=65536, N=256, K=256)
    sgemm_nt<<<dim3(256 / 128, TOK / 128), 256>>>(p_g, NH, p_wc, NH, p_bc,
                                                  p_feats, 256, NH);

    // 5. router epilogue
    router_kernel<<<TOK / 8, 256>>>(Wc2, bc2, Wk2, bk2, out);

    // 6. losses
    finalize_kernel<<<1, 1>>>(out);
}

// round 14
// speedup vs baseline: 1.3281x; 1.3281x over previous
#include <cuda_runtime.h>
#include <cstdint>
#include <math.h>

// ---------------------------------------------------------------- constants
#define NB   32
#define NS   2048
#define ND   768
#define NE   8
#define NH   256
#define TOK  (NB*NS)          // 65536
#define G3   (3*NH)           // 768

// output layout (float32, concatenated flattened tuple)
#define OUT_EW   0
#define OUT_IDX  (TOK*4)                // 262144
#define OUT_RW   (TOK*8)                // 524288
#define OUT_NH   (OUT_RW + TOK*8)       // 1048576
#define OUT_C    (OUT_NH + NB*NH)       // 1056768
#define OUT_LB   (OUT_C + TOK)          // 1122304
#define OUT_CR   (OUT_LB + 1)           // 1122305

// ---------------------------------------------------------------- scratch
__device__ float  g_gi[(size_t)TOK * G3];     // [B*S, 768]
__device__ float  g_g [(size_t)TOK * NH];     // [B*S, 256]
__device__ float  g_feats[(size_t)TOK * 256]; // heads gemm out
__device__ float  g_Wcomb[256 * 256];
__device__ float  g_bcomb[256];
__device__ double g_acc[9];                   // 8 usage sums + complexity^2 sum

// ---------------------------------------------------------------- helpers
__device__ __forceinline__ unsigned long long dup2f(float x) {
    unsigned long long r;
    asm("mov.b64 %0, {%1, %1};" : "=l"(r) : "f"(x));
    return r;
}
__device__ __forceinline__ void fma2(unsigned long long& acc,
                                     unsigned long long a, unsigned long long b) {
    asm("fma.rn.f32x2 %0, %1, %2, %0;" : "+l"(acc) : "l"(a), "l"(b));
}
__device__ __forceinline__ float2 unpack2(unsigned long long v) {
    float2 f;
    asm("mov.b64 {%0, %1}, %2;" : "=f"(f.x), "=f"(f.y) : "l"(v));
    return f;
}
__device__ __forceinline__ uint32_t smem_u32(const void* p) {
    uint32_t a;
    asm("{ .reg .u64 t; cvta.to.shared.u64 t, %1; cvt.u32.u64 %0, t; }"
        : "=r"(a) : "l"(p));
    return a;
}
__device__ __forceinline__ void st_cluster_f32(uint32_t saddr, uint32_t rank, float v) {
    uint32_t r;
    asm volatile("mapa.shared::cluster.u32 %0, %1, %2;" : "=r"(r) : "r"(saddr), "r"(rank));
    asm volatile("st.shared::cluster.f32 [%0], %1;" :: "r"(r), "f"(v) : "memory");
}
__device__ __forceinline__ void cluster_arrive_() {
    asm volatile("barrier.cluster.arrive.aligned;" ::: "memory");
}
__device__ __forceinline__ void cluster_wait_() {
    asm volatile("barrier.cluster.wait.aligned;" ::: "memory");
}
__device__ __forceinline__ void cluster_sync_() {
    cluster_arrive_(); cluster_wait_();
}
// fast gate math: MUFU-based (round-11 proven; 1 near-tie flip -> 6.6e-4)
__device__ __forceinline__ float fast_sigmoid(float x) {
    return __fdividef(1.f, 1.f + __expf(-x));
}
__device__ __forceinline__ float fast_tanh(float x) {
    return 1.f - __fdividef(2.f, __expf(2.f * x) + 1.f);
}

// ============================================================== SGEMM (NT)
// C[m][n] = sum_k A[m][k]*B[n][k] + bias[n]
// BM=BN=128, BK=16, 256 threads, 8x8 per thread via f32x2.
// Double-buffered smem: one __syncthreads per tile (round-13 proven).
__global__ __launch_bounds__(256, 2)
void sgemm_nt(const float* __restrict__ A, int lda,
              const float* __restrict__ B, int ldb,
              const float* __restrict__ bias,
              float* __restrict__ C, int ldc, int K)
{
    __shared__ float As[2][16 * 128];
    __shared__ float Bs[2][16 * 128];

    const int tid = threadIdx.x;
    const int tx  = tid & 15, ty = tid >> 4;
    const int tx4 = tx * 4,  ty4 = ty * 4;
    const size_t bm = (size_t)blockIdx.y * 128;
    const size_t bn = (size_t)blockIdx.x * 128;

    const int r0 = tid >> 2;          // 0..63
    const int r1 = r0 + 64;
    const int c4 = (tid & 3) * 4;     // 0,4,8,12

    const float* Ag0 = A + (bm + r0) * (size_t)lda + c4;
    const float* Ag1 = A + (bm + r1) * (size_t)lda + c4;
    const float* Bg0 = B + (bn + r0) * (size_t)ldb + c4;
    const float* Bg1 = B + (bn + r1) * (size_t)ldb + c4;

    unsigned long long acc[8][4];
#pragma unroll
    for (int i = 0; i < 8; i++)
#pragma unroll
        for (int jp = 0; jp < 4; jp++) acc[i][jp] = 0ull;

    // chunk 0 -> buffer 0
    float4 pa0 = *(const float4*)Ag0;
    float4 pa1 = *(const float4*)Ag1;
    float4 pb0 = *(const float4*)Bg0;
    float4 pb1 = *(const float4*)Bg1;
#pragma unroll
    for (int jj = 0; jj < 4; jj++) {
        As[0][(c4 + jj) * 128 + r0] = ((const float*)&pa0)[jj];
        As[0][(c4 + jj) * 128 + r1] = ((const float*)&pa1)[jj];
        Bs[0][(c4 + jj) * 128 + r0] = ((const float*)&pb0)[jj];
        Bs[0][(c4 + jj) * 128 + r1] = ((const float*)&pb1)[jj];
    }
    __syncthreads();

    const int nk = K >> 4;
    int p = 0;
    for (int kt = 0; kt < nk; kt++) {
        const bool has_next = (kt + 1 < nk);
        if (has_next) {
            const int off = (kt + 1) * 16;
            pa0 = *(const float4*)(Ag0 + off);
            pa1 = *(const float4*)(Ag1 + off);
            pb0 = *(const float4*)(Bg0 + off);
            pb1 = *(const float4*)(Bg1 + off);
        }

        const float* asb = As[p];
        const float* bsb = Bs[p];
#pragma unroll
        for (int k = 0; k < 16; k++) {
            const float* asr = asb + k * 128;
            float4 a0 = *(const float4*)(asr + ty4);
            float4 a1 = *(const float4*)(asr + 64 + ty4);
            const ulonglong2* bsr = (const ulonglong2*)(bsb + k * 128);
            ulonglong2 b0 = bsr[tx];
            ulonglong2 b1 = bsr[16 + tx];
            float am[8] = {a0.x, a0.y, a0.z, a0.w, a1.x, a1.y, a1.z, a1.w};
#pragma unroll
            for (int i = 0; i < 8; i++) {
                unsigned long long ad = dup2f(am[i]);
                fma2(acc[i][0], ad, b0.x);
                fma2(acc[i][1], ad, b0.y);
                fma2(acc[i][2], ad, b1.x);
                fma2(acc[i][3], ad, b1.y);
            }
        }

        if (has_next) {
            float* ad_ = As[p ^ 1];
            float* bd_ = Bs[p ^ 1];
#pragma unroll
            for (int jj = 0; jj < 4; jj++) {
                ad_[(c4 + jj) * 128 + r0] = ((const float*)&pa0)[jj];
                ad_[(c4 + jj) * 128 + r1] = ((const float*)&pa1)[jj];
                bd_[(c4 + jj) * 128 + r0] = ((const float*)&pb0)[jj];
                bd_[(c4 + jj) * 128 + r1] = ((const float*)&pb1)[jj];
            }
        }
        __syncthreads();   // single barrier per tile
        p ^= 1;
    }

    float4 bb0 = *(const float4*)(bias + bn + tx4);
    float4 bb1 = *(const float4*)(bias + bn + 64 + tx4);

#pragma unroll
    for (int i = 0; i < 8; i++) {
        size_t m = bm + (size_t)((i < 4) ? (ty4 + i) : (64 + ty4 + (i - 4)));
        float2 p0 = unpack2(acc[i][0]);
        float2 p1 = unpack2(acc[i][1]);
        float2 p2 = unpack2(acc[i][2]);
        float2 p3 = unpack2(acc[i][3]);
        float4 o0 = make_float4(p0.x + bb0.x, p0.y + bb0.y, p1.x + bb0.z, p1.y + bb0.w);
        float4 o1 = make_float4(p2.x + bb1.x, p2.y + bb1.y, p3.x + bb1.z, p3.y + bb1.w);
        *(float4*)&C[m * (size_t)ldc + bn + tx4]      = o0;
        *(float4*)&C[m * (size_t)ldc + bn + 64 + tx4] = o1;
    }
}

// ============================================================== GRU scan
// EXACT round-11 version (measured best): one batch per 4-CTA cluster,
// register-resident W_hh (2 threads/row, 128 K each), single intra-CTA
// barrier, fast MUFU gates, hoisted hold-load, split cluster barrier with
// the gout STG inside the wait shadow.
// (Round-13 2-batch variant regressed ~+1300us: register spills in gemv.)
#define GRU_THREADS 384

__global__ void __cluster_dims__(4, 1, 1) __launch_bounds__(GRU_THREADS, 1)
gru_kernel(const float* __restrict__ W_hh, const float* __restrict__ b_hh,
           float* __restrict__ out_hidden)
{
    __shared__ float hb[2][256];            // double-buffered hidden state
    __shared__ float ps[GRU_THREADS];       // partial sums (half0 | half1)

    const int tid  = threadIdx.x;
    const int rank = blockIdx.x;            // 0..3
    const int b    = blockIdx.y;            // 0..31
    const int half = (tid >= 192) ? 1 : 0;  // K-half (warp-uniform)
    const int r    = tid - half * 192;      // row 0..191  (= g*64 + j)
    const int g    = r >> 6;
    const int j    = r & 63;
    const int u    = rank * 64 + tid;       // unit id (valid only for tid<64)

    ulonglong2 w[32];
    {
        const ulonglong2* src = (const ulonglong2*)
            (W_hh + ((size_t)(g * 256 + rank * 64 + j)) * 256 + half * 128);
#pragma unroll
        for (int i = 0; i < 32; i++) w[i] = src[i];
    }

    if (tid < 256) { hb[0][tid] = 0.f; hb[1][tid] = 0.f; }

    float bhr = 0.f, bhz = 0.f, bhn = 0.f;
    if (tid < 64) {
        bhr = b_hh[u]; bhz = b_hh[256 + u]; bhn = b_hh[512 + u];
    }
    __syncthreads();
    cluster_sync_();

    const float* gi_base = g_gi + (size_t)b * NS * G3;
    float*       gout    = g_g  + (size_t)b * NS * NH;
    const uint32_t hb_u32 = smem_u32(&hb[0][0]);

    float cr = 0.f, cz = 0.f, cn = 0.f;
    if (tid < 64) { cr = gi_base[u]; cz = gi_base[256 + u]; cn = gi_base[512 + u]; }

    int p = 0;
#pragma unroll 1
    for (int t = 0; t < NS; t++) {
        // prefetch gi(t+1) — consumed a full step later, hides LDG latency
        float nr = 0.f, nz = 0.f, nn = 0.f;
        if (tid < 64 && t + 1 < NS) {
            const float* gn_ = gi_base + (size_t)(t + 1) * G3;
            nr = gn_[u]; nz = gn_[256 + u]; nn = gn_[512 + u];
        }

        // gemv: 128-MAC partial dot from register W, broadcast-LDS h
        const ulonglong2* hv = (const ulonglong2*)(&hb[p][half * 128]);
        unsigned long long a0 = 0ull, a1 = 0ull, a2 = 0ull, a3 = 0ull;
#pragma unroll
        for (int i = 0; i < 32; i += 2) {
            ulonglong2 h0 = hv[i], h1 = hv[i + 1];
            fma2(a0, w[i].x,     h0.x);
            fma2(a1, w[i].y,     h0.y);
            fma2(a2, w[i + 1].x, h1.x);
            fma2(a3, w[i + 1].y, h1.y);
        }
        float2 f0 = unpack2(a0), f1 = unpack2(a1), f2 = unpack2(a2), f3 = unpack2(a3);
        ps[tid] = ((f0.x + f0.y) + (f1.x + f1.y)) + ((f2.x + f2.y) + (f3.x + f3.y));
        __syncthreads();   // the ONLY intra-CTA barrier per step

        float hnew = 0.f;
        if (tid < 64) {
            float hold = hb[p][u];                 // hoisted: overlap LDS latency
            float hr = ps[tid]       + ps[192 + tid];
            float hz = ps[64 + tid]  + ps[256 + tid];
            float hn = ps[128 + tid] + ps[320 + tid];
            float rr = fast_sigmoid(cr + bhr + hr);
            float zz = fast_sigmoid(cz + bhz + hz);
            float n2 = fast_tanh(cn + bhn + rr * hn);
            hnew = (1.f - zz) * n2 + zz * hold;

            uint32_t dst = hb_u32 + (uint32_t)((((p ^ 1) * 256) + u) * 4);
#pragma unroll
            for (int c = 0; c < 4; c++)
                st_cluster_f32(dst, (uint32_t)c, hnew);   // h(t+1) to CTA c
        }
        // split barrier: arrive (release covers remote stores), then do the
        // global-memory writes inside the wait shadow, then wait.
        cluster_arrive_();
        if (tid < 64) {
            gout[(size_t)t * NH + u] = hnew;
            if (t == NS - 1) out_hidden[b * NH + u] = hnew;
        }
        cluster_wait_();
        p ^= 1;
        cr = nr; cz = nz; cn = nn;
    }
    cluster_sync_();
}

// ============================================================== prep
__global__ void prep_kernel(const float* __restrict__ Wc1, const float* __restrict__ bc1,
                            const float* __restrict__ Wr,  const float* __restrict__ br,
                            const float* __restrict__ Wk1, const float* __restrict__ bk1)
{
    int r = blockIdx.x, c = threadIdx.x;
    float v = 0.f, bv = 0.f;
    if (r < 128)       { v = Wc1[r * 256 + c];         bv = bc1[r];       }
    else if (r < 136)  { v = Wr [(r - 128) * 256 + c]; bv = br [r - 128]; }
    else if (r < 200)  { v = Wk1[(r - 136) * 256 + c]; bv = bk1[r - 136]; }
    g_Wcomb[r * 256 + c] = v;
    if (c == 0) g_bcomb[r] = bv;
    if (r == 0 && c < 9) g_acc[c] = 0.0;
}

// ============================================================== router
__global__ __launch_bounds__(256)
void router_kernel(const float* __restrict__ Wc2, const float* __restrict__ bc2,
                   const float* __restrict__ Wk2, const float* __restrict__ bk2,
                   float* __restrict__ out)
{
    __shared__ double sacc[9];
    const int tid = threadIdx.x;
    if (tid < 9) sacc[tid] = 0.0;
    __syncthreads();

    const int warp = tid >> 5, lane = tid & 31;
    const int i = blockIdx.x * 8 + warp;
    const float* row = g_feats + (size_t)i * 256;

    float4 f = *(const float4*)(row + lane * 4);
    float4 w = *(const float4*)(Wc2 + lane * 4);
    float s = fmaxf(f.x, 0.f) * w.x + fmaxf(f.y, 0.f) * w.y +
              fmaxf(f.z, 0.f) * w.z + fmaxf(f.w, 0.f) * w.w;
    float2 f2 = *(const float2*)(row + 136 + lane * 2);
    float2 w2 = *(const float2*)(Wk2 + lane * 2);
    float s2 = fmaxf(f2.x, 0.f) * w2.x + fmaxf(f2.y, 0.f) * w2.y;
#pragma unroll
    for (int o = 16; o > 0; o >>= 1) {
        s  += __shfl_xor_sync(0xffffffffu, s,  o);
        s2 += __shfl_xor_sync(0xffffffffu, s2, o);
    }

    if (lane == 0) {
        // precise expf: router outputs are directly compared
        float comp = 1.f / (1.f + expf(-(s + bc2[0])));
        float tsc  = 1.f / (1.f + expf(-(s2 + bk2[0])));

        float lg[NE];
        float mx = -1e30f;
#pragma unroll
        for (int e = 0; e < NE; e++) { lg[e] = row[128 + e]; mx = fmaxf(mx, lg[e]); }
        float sum = 0.f;
#pragma unroll
        for (int e = 0; e < NE; e++) { lg[e] = expf(lg[e] - mx); sum += lg[e]; }
        float inv = 1.f / sum;
        float rw[NE];
#pragma unroll
        for (int e = 0; e < NE; e++) {
            rw[e] = lg[e] * inv;
            out[OUT_RW + (size_t)i * NE + e] = rw[e];
        }

        int   idx[4];
        float tv[4];
        bool  used[NE] = {false, false, false, false, false, false, false, false};
#pragma unroll
        for (int s4 = 0; s4 < 4; s4++) {
            int best = 0; float bv = -1e30f;
#pragma unroll
            for (int e = 0; e < NE; e++)
                if (!used[e] && rw[e] > bv) { bv = rw[e]; best = e; }
            used[best] = true; tv[s4] = bv; idx[s4] = best;
        }

        float combined = 0.7f * comp + 0.3f * tsc;
        int kk = (int)rintf(1.f + combined * 3.f);
        if (kk < 1) kk = 1; if (kk > 4) kk = 4;

        float ms = 0.f, mw[4];
#pragma unroll
        for (int s4 = 0; s4 < 4; s4++) { mw[s4] = (s4 < kk) ? tv[s4] : 0.f; ms += mw[s4]; }
        if (!(ms > 0.f)) ms = 1.f;
        float im = 1.f / ms;
#pragma unroll
        for (int s4 = 0; s4 < 4; s4++) {
            out[OUT_EW  + (size_t)i * 4 + s4] = mw[s4] * im;
            out[OUT_IDX + (size_t)i * 4 + s4] = (float)idx[s4];
        }
        out[OUT_C + i] = comp;

#pragma unroll
        for (int e = 0; e < NE; e++) atomicAdd(&sacc[e], (double)rw[e]);
        atomicAdd(&sacc[8], (double)comp * (double)comp);
    }
    __syncthreads();
    if (tid < 9) atomicAdd(&g_acc[tid], sacc[tid]);
}

// ============================================================== finalize
__global__ void finalize_kernel(float* __restrict__ out)
{
    double s = 0.0;
#pragma unroll
    for (int e = 0; e < NE; e++) {
        double u = g_acc[e] / (double)TOK - 1.0 / (double)NE;
        s += u * u;
    }
    out[OUT_LB] = (float)(s / (double)NE * 0.01);
    out[OUT_CR] = (float)(g_acc[8] / (double)TOK * 0.001);
}

// ============================================================== launch
extern "C" void kernel_launch(void* const* d_in, const int* in_sizes, int n_in,
                              void* d_out, int out_size)
{
    (void)in_sizes; (void)n_in; (void)out_size;
    const float* x    = (const float*)d_in[0];
    // d_in[1] = layer_idx (unused)
    const float* W_ih = (const float*)d_in[2];   // [768, 776]
    const float* W_hh = (const float*)d_in[3];   // [768, 256]
    const float* b_ih = (const float*)d_in[4];
    const float* b_hh = (const float*)d_in[5];
    const float* Wc1  = (const float*)d_in[6];
    const float* bc1  = (const float*)d_in[7];
    const float* Wc2  = (const float*)d_in[8];
    const float* bc2  = (const float*)d_in[9];
    const float* Wr   = (const float*)d_in[10];
    const float* br   = (const float*)d_in[11];
    const float* Wk1  = (const float*)d_in[12];
    const float* bk1  = (const float*)d_in[13];
    const float* Wk2  = (const float*)d_in[14];
    const float* bk2  = (const float*)d_in[15];
    float* out = (float*)d_out;

    static float* p_gi = nullptr;
    static float* p_g = nullptr;
    static float* p_feats = nullptr;
    static float* p_wc = nullptr;
    static float* p_bc = nullptr;
    if (!p_gi) {
        cudaGetSymbolAddress((void**)&p_gi,    g_gi);
        cudaGetSymbolAddress((void**)&p_g,     g_g);
        cudaGetSymbolAddress((void**)&p_feats, g_feats);
        cudaGetSymbolAddress((void**)&p_wc,    g_Wcomb);
        cudaGetSymbolAddress((void**)&p_bc,    g_bcomb);
    }

    // 1. pack head weights + zero loss accumulators
    prep_kernel<<<256, 256>>>(Wc1, bc1, Wr, br, Wk1, bk1);

    // 2. gi = x @ W_ih[:, :768]^T + b_ih   (M=65536, N=768, K=768)
    sgemm_nt<<<dim3(G3 / 128, TOK / 128), 256>>>(x, ND, W_ih, ND + NE, b_ih,
                                                 p_gi, G3, ND);

    // 3. GRU scan (one batch per 4-CTA cluster; round-11 proven)
    gru_kernel<<<dim3(4, NB), GRU_THREADS>>>(W_hh, b_hh, out + OUT_NH);

    // 4. heads: feats = g @ Wcomb^T + bcomb   (M=65536, N=256, K=256)
    sgemm_nt<<<dim3(256 / 128, TOK / 128), 256>>>(p_g, NH, p_wc, NH, p_bc,
                                                  p_feats, 256, NH);

    // 5. router epilogue
    router_kernel<<<TOK / 8, 256>>>(Wc2, bc2, Wk2, bk2, out);

    // 6. losses
    finalize_kernel<<<1, 1>>>(out);
}

// round 15
// speedup vs baseline: 1.4740x; 1.1098x over previous
#include <cuda_runtime.h>
#include <cstdint>
#include <math.h>

// ---------------------------------------------------------------- constants
#define NB   32
#define NS   2048
#define ND   768
#define NE   8
#define NH   256
#define TOK  (NB*NS)          // 65536
#define G3   (3*NH)           // 768

// output layout (float32, concatenated flattened tuple)
#define OUT_EW   0
#define OUT_IDX  (TOK*4)                // 262144
#define OUT_RW   (TOK*8)                // 524288
#define OUT_NH   (OUT_RW + TOK*8)       // 1048576
#define OUT_C    (OUT_NH + NB*NH)       // 1056768
#define OUT_LB   (OUT_C + TOK)          // 1122304
#define OUT_CR   (OUT_LB + 1)           // 1122305

// ---------------------------------------------------------------- scratch
__device__ float  g_gi[(size_t)TOK * G3];     // [B*S, 768]
__device__ float  g_g [(size_t)TOK * NH];     // [B*S, 256]
__device__ float  g_feats[(size_t)TOK * 256]; // heads gemm out
__device__ float  g_Wcomb[256 * 256];
__device__ float  g_bcomb[256];
__device__ double g_acc[9];                   // 8 usage sums + complexity^2 sum

// ---------------------------------------------------------------- helpers
__device__ __forceinline__ unsigned long long dup2f(float x) {
    unsigned long long r;
    asm("mov.b64 %0, {%1, %1};" : "=l"(r) : "f"(x));
    return r;
}
__device__ __forceinline__ void fma2(unsigned long long& acc,
                                     unsigned long long a, unsigned long long b) {
    asm("fma.rn.f32x2 %0, %1, %2, %0;" : "+l"(acc) : "l"(a), "l"(b));
}
__device__ __forceinline__ float2 unpack2(unsigned long long v) {
    float2 f;
    asm("mov.b64 {%0, %1}, %2;" : "=f"(f.x), "=f"(f.y) : "l"(v));
    return f;
}
__device__ __forceinline__ uint32_t smem_u32(const void* p) {
    uint32_t a;
    asm("{ .reg .u64 t; cvta.to.shared.u64 t, %1; cvt.u32.u64 %0, t; }"
        : "=r"(a) : "l"(p));
    return a;
}
__device__ __forceinline__ void cluster_arrive_() {
    asm volatile("barrier.cluster.arrive.aligned;" ::: "memory");
}
__device__ __forceinline__ void cluster_wait_() {
    asm volatile("barrier.cluster.wait.aligned;" ::: "memory");
}
__device__ __forceinline__ void cluster_sync_() {
    cluster_arrive_(); cluster_wait_();
}
// fast gate math: MUFU-based (round-11 proven)
__device__ __forceinline__ float fast_sigmoid(float x) {
    return __fdividef(1.f, 1.f + __expf(-x));
}
__device__ __forceinline__ float fast_tanh(float x) {
    return 1.f - __fdividef(2.f, __expf(2.f * x) + 1.f);
}
// st.async: data store carries mbarrier tx-completion (no arrive storm).
// addr/mbar are local smem offsets; both get mapa'd to target CTA `rank`.
__device__ __forceinline__ void st_async_f32(uint32_t addr, uint32_t mbar,
                                             uint32_t rank, float v) {
    asm volatile(
        "{\n\t.reg .b32 ra, rb;\n\t"
        "mapa.shared::cluster.u32 ra, %0, %2;\n\t"
        "mapa.shared::cluster.u32 rb, %1, %2;\n\t"
        "st.async.weak.shared::cluster.mbarrier::complete_tx::bytes.b32 [ra], %3, [rb];\n\t"
        "}" :: "r"(addr), "r"(mbar), "r"(rank), "f"(v) : "memory");
}
// one local arrival + expected tx bytes for this phase
__device__ __forceinline__ void mbar_arrive_expect_tx(uint32_t mbar, uint32_t bytes) {
    asm volatile("mbarrier.arrive.expect_tx.shared.b64 _, [%0], %1;"
                 :: "r"(mbar), "r"(bytes) : "memory");
}
// parity wait, acquire at cluster scope (round-7-proven syntax)
__device__ __forceinline__ void mbar_wait_(uint32_t addr, uint32_t parity) {
    uint32_t done;
    asm volatile(
        "{\n\t.reg .pred p;\n\t"
        "mbarrier.try_wait.parity.acquire.cluster.shared::cta.b64 p, [%1], %2;\n\t"
        "selp.b32 %0, 1, 0, p;\n\t}"
        : "=r"(done) : "r"(addr), "r"(parity) : "memory");
    if (!done) {
        asm volatile(
            "{\n\t.reg .pred P1;\n\t"
            "WAITLP_%=:\n\t"
            "mbarrier.try_wait.parity.acquire.cluster.shared::cta.b64 P1, [%0], %1, 0x989680;\n\t"
            "@!P1 bra WAITLP_%=;\n\t"
            "}" :: "r"(addr), "r"(parity) : "memory");
    }
}

// ============================================================== SGEMM (NT)
// Round-14 proven: double-buffered, one __syncthreads per BK=16 tile.
__global__ __launch_bounds__(256, 2)
void sgemm_nt(const float* __restrict__ A, int lda,
              const float* __restrict__ B, int ldb,
              const float* __restrict__ bias,
              float* __restrict__ C, int ldc, int K)
{
    __shared__ float As[2][16 * 128];
    __shared__ float Bs[2][16 * 128];

    const int tid = threadIdx.x;
    const int tx  = tid & 15, ty = tid >> 4;
    const int tx4 = tx * 4,  ty4 = ty * 4;
    const size_t bm = (size_t)blockIdx.y * 128;
    const size_t bn = (size_t)blockIdx.x * 128;

    const int r0 = tid >> 2;          // 0..63
    const int r1 = r0 + 64;
    const int c4 = (tid & 3) * 4;     // 0,4,8,12

    const float* Ag0 = A + (bm + r0) * (size_t)lda + c4;
    const float* Ag1 = A + (bm + r1) * (size_t)lda + c4;
    const float* Bg0 = B + (bn + r0) * (size_t)ldb + c4;
    const float* Bg1 = B + (bn + r1) * (size_t)ldb + c4;

    unsigned long long acc[8][4];
#pragma unroll
    for (int i = 0; i < 8; i++)
#pragma unroll
        for (int jp = 0; jp < 4; jp++) acc[i][jp] = 0ull;

    float4 pa0 = *(const float4*)Ag0;
    float4 pa1 = *(const float4*)Ag1;
    float4 pb0 = *(const float4*)Bg0;
    float4 pb1 = *(const float4*)Bg1;
#pragma unroll
    for (int jj = 0; jj < 4; jj++) {
        As[0][(c4 + jj) * 128 + r0] = ((const float*)&pa0)[jj];
        As[0][(c4 + jj) * 128 + r1] = ((const float*)&pa1)[jj];
        Bs[0][(c4 + jj) * 128 + r0] = ((const float*)&pb0)[jj];
        Bs[0][(c4 + jj) * 128 + r1] = ((const float*)&pb1)[jj];
    }
    __syncthreads();

    const int nk = K >> 4;
    int p = 0;
    for (int kt = 0; kt < nk; kt++) {
        const bool has_next = (kt + 1 < nk);
        if (has_next) {
            const int off = (kt + 1) * 16;
            pa0 = *(const float4*)(Ag0 + off);
            pa1 = *(const float4*)(Ag1 + off);
            pb0 = *(const float4*)(Bg0 + off);
            pb1 = *(const float4*)(Bg1 + off);
        }

        const float* asb = As[p];
        const float* bsb = Bs[p];
#pragma unroll
        for (int k = 0; k < 16; k++) {
            const float* asr = asb + k * 128;
            float4 a0 = *(const float4*)(asr + ty4);
            float4 a1 = *(const float4*)(asr + 64 + ty4);
            const ulonglong2* bsr = (const ulonglong2*)(bsb + k * 128);
            ulonglong2 b0 = bsr[tx];
            ulonglong2 b1 = bsr[16 + tx];
            float am[8] = {a0.x, a0.y, a0.z, a0.w, a1.x, a1.y, a1.z, a1.w};
#pragma unroll
            for (int i = 0; i < 8; i++) {
                unsigned long long ad = dup2f(am[i]);
                fma2(acc[i][0], ad, b0.x);
                fma2(acc[i][1], ad, b0.y);
                fma2(acc[i][2], ad, b1.x);
                fma2(acc[i][3], ad, b1.y);
            }
        }

        if (has_next) {
            float* ad_ = As[p ^ 1];
            float* bd_ = Bs[p ^ 1];
#pragma unroll
            for (int jj = 0; jj < 4; jj++) {
                ad_[(c4 + jj) * 128 + r0] = ((const float*)&pa0)[jj];
                ad_[(c4 + jj) * 128 + r1] = ((const float*)&pa1)[jj];
                bd_[(c4 + jj) * 128 + r0] = ((const float*)&pb0)[jj];
                bd_[(c4 + jj) * 128 + r1] = ((const float*)&pb1)[jj];
            }
        }
        __syncthreads();
        p ^= 1;
    }

    float4 bb0 = *(const float4*)(bias + bn + tx4);
    float4 bb1 = *(const float4*)(bias + bn + 64 + tx4);

#pragma unroll
    for (int i = 0; i < 8; i++) {
        size_t m = bm + (size_t)((i < 4) ? (ty4 + i) : (64 + ty4 + (i - 4)));
        float2 p0 = unpack2(acc[i][0]);
        float2 p1 = unpack2(acc[i][1]);
        float2 p2 = unpack2(acc[i][2]);
        float2 p3 = unpack2(acc[i][3]);
        float4 o0 = make_float4(p0.x + bb0.x, p0.y + bb0.y, p1.x + bb0.z, p1.y + bb0.w);
        float4 o1 = make_float4(p2.x + bb1.x, p2.y + bb1.y, p3.x + bb1.z, p3.y + bb1.w);
        *(float4*)&C[m * (size_t)ldc + bn + tx4]      = o0;
        *(float4*)&C[m * (size_t)ldc + bn + 64 + tx4] = o1;
    }
}

// ============================================================== GRU scan
// Round-11 structure; per-step cluster.sync (~490cyc) + DSMEM-store wait
// replaced by st.async with mbarrier tx-bytes accounting:
//   - gate threads st.async h(t+1) to all 4 CTAs (store carries completion)
//   - tid0 posts arrive.expect_tx(1024B = 256 units x 4B) per step
//   - all threads try_wait parity (wakeup ~60-150cyc)
// Two alternating barriers; signed tx-count absorbs expect/store races;
// +/-1-phase skew bound holds because step t+1 stores require the step t wait.
#define GRU_THREADS 384

__global__ void __cluster_dims__(4, 1, 1) __launch_bounds__(GRU_THREADS, 1)
gru_kernel(const float* __restrict__ W_hh, const float* __restrict__ b_hh,
           float* __restrict__ out_hidden)
{
    __shared__ float hb[2][256];            // double-buffered hidden state
    __shared__ float ps[GRU_THREADS];       // partial sums (half0 | half1)
    __shared__ __align__(8) unsigned long long bar[2];

    const int tid  = threadIdx.x;
    const int rank = blockIdx.x;            // 0..3
    const int b    = blockIdx.y;            // 0..31
    const int half = (tid >= 192) ? 1 : 0;  // K-half (warp-uniform)
    const int r    = tid - half * 192;      // row 0..191  (= g*64 + j)
    const int g    = r >> 6;
    const int j    = r & 63;
    const int u    = rank * 64 + tid;       // unit id (valid only for tid<64)

    ulonglong2 w[32];
    {
        const ulonglong2* src = (const ulonglong2*)
            (W_hh + ((size_t)(g * 256 + rank * 64 + j)) * 256 + half * 128);
#pragma unroll
        for (int i = 0; i < 32; i++) w[i] = src[i];
    }

    if (tid < 256) { hb[0][tid] = 0.f; hb[1][tid] = 0.f; }

    const uint32_t bar0 = smem_u32(&bar[0]);
    const uint32_t bar1 = smem_u32(&bar[1]);
    if (tid == 0) {
        asm volatile("mbarrier.init.shared.b64 [%0], 1;" :: "r"(bar0) : "memory");
        asm volatile("mbarrier.init.shared.b64 [%0], 1;" :: "r"(bar1) : "memory");
    }

    float bhr = 0.f, bhz = 0.f, bhn = 0.f;
    if (tid < 64) {
        bhr = b_hh[u]; bhz = b_hh[256 + u]; bhn = b_hh[512 + u];
    }
    __syncthreads();
    cluster_sync_();   // all CTAs' barriers initialized before any remote store

    const float* gi_base = g_gi + (size_t)b * NS * G3;
    float*       gout    = g_g  + (size_t)b * NS * NH;
    const uint32_t hb_u32 = smem_u32(&hb[0][0]);

    float cr = 0.f, cz = 0.f, cn = 0.f;
    if (tid < 64) { cr = gi_base[u]; cz = gi_base[256 + u]; cn = gi_base[512 + u]; }

    int p = 0;
#pragma unroll 1
    for (int t = 0; t < NS; t++) {
        const uint32_t barx = (t & 1) ? bar1 : bar0;
        // post this phase's expected tx (1 arrival + 1024 bytes).
        // Early remote completions drive tx negative; expect rebalances. Safe.
        if (tid == 0) mbar_arrive_expect_tx(barx, 1024);

        // prefetch gi(t+1)
        float nr = 0.f, nz = 0.f, nn = 0.f;
        if (tid < 64 && t + 1 < NS) {
            const float* gn_ = gi_base + (size_t)(t + 1) * G3;
            nr = gn_[u]; nz = gn_[256 + u]; nn = gn_[512 + u];
        }

        // gemv: 128-MAC partial dot from register W, broadcast-LDS h
        const ulonglong2* hv = (const ulonglong2*)(&hb[p][half * 128]);
        unsigned long long a0 = 0ull, a1 = 0ull, a2 = 0ull, a3 = 0ull;
#pragma unroll
        for (int i = 0; i < 32; i += 2) {
            ulonglong2 h0 = hv[i], h1 = hv[i + 1];
            fma2(a0, w[i].x,     h0.x);
            fma2(a1, w[i].y,     h0.y);
            fma2(a2, w[i + 1].x, h1.x);
            fma2(a3, w[i + 1].y, h1.y);
        }
        float2 f0 = unpack2(a0), f1 = unpack2(a1), f2 = unpack2(a2), f3 = unpack2(a3);
        ps[tid] = ((f0.x + f0.y) + (f1.x + f1.y)) + ((f2.x + f2.y) + (f3.x + f3.y));
        __syncthreads();   // the ONLY intra-CTA barrier per step

        float hnew = 0.f;
        if (tid < 64) {
            float hold = hb[p][u];
            float hr = ps[tid]       + ps[192 + tid];
            float hz = ps[64 + tid]  + ps[256 + tid];
            float hn = ps[128 + tid] + ps[320 + tid];
            float rr = fast_sigmoid(cr + bhr + hr);
            float zz = fast_sigmoid(cz + bhz + hz);
            float n2 = fast_tanh(cn + bhn + rr * hn);
            hnew = (1.f - zz) * n2 + zz * hold;

            // h(t+1) to all 4 CTAs; each store signals 4 tx bytes
            uint32_t dst = hb_u32 + (uint32_t)((((p ^ 1) * 256) + u) * 4);
#pragma unroll
            for (int c = 0; c < 4; c++)
                st_async_f32(dst, barx, (uint32_t)c, hnew);

            // global writes in the wait shadow
            gout[(size_t)t * NH + u] = hnew;
            if (t == NS - 1) out_hidden[b * NH + u] = hnew;
        }
        mbar_wait_(barx, (uint32_t)((t >> 1) & 1));
        p ^= 1;
        cr = nr; cz = nz; cn = nn;
    }
    // no CTA exits while peers may still st.async into its smem
    cluster_sync_();
}

// ============================================================== prep
__global__ void prep_kernel(const float* __restrict__ Wc1, const float* __restrict__ bc1,
                            const float* __restrict__ Wr,  const float* __restrict__ br,
                            const float* __restrict__ Wk1, const float* __restrict__ bk1)
{
    int r = blockIdx.x, c = threadIdx.x;
    float v = 0.f, bv = 0.f;
    if (r < 128)       { v = Wc1[r * 256 + c];         bv = bc1[r];       }
    else if (r < 136)  { v = Wr [(r - 128) * 256 + c]; bv = br [r - 128]; }
    else if (r < 200)  { v = Wk1[(r - 136) * 256 + c]; bv = bk1[r - 136]; }
    g_Wcomb[r * 256 + c] = v;
    if (c == 0) g_bcomb[r] = bv;
    if (r == 0 && c < 9) g_acc[c] = 0.0;
}

// ============================================================== router
__global__ __launch_bounds__(256)
void router_kernel(const float* __restrict__ Wc2, const float* __restrict__ bc2,
                   const float* __restrict__ Wk2, const float* __restrict__ bk2,
                   float* __restrict__ out)
{
    __shared__ double sacc[9];
    const int tid = threadIdx.x;
    if (tid < 9) sacc[tid] = 0.0;
    __syncthreads();

    const int warp = tid >> 5, lane = tid & 31;
    const int i = blockIdx.x * 8 + warp;
    const float* row = g_feats + (size_t)i * 256;

    float4 f = *(const float4*)(row + lane * 4);
    float4 w = *(const float4*)(Wc2 + lane * 4);
    float s = fmaxf(f.x, 0.f) * w.x + fmaxf(f.y, 0.f) * w.y +
              fmaxf(f.z, 0.f) * w.z + fmaxf(f.w, 0.f) * w.w;
    float2 f2 = *(const float2*)(row + 136 + lane * 2);
    float2 w2 = *(const float2*)(Wk2 + lane * 2);
    float s2 = fmaxf(f2.x, 0.f) * w2.x + fmaxf(f2.y, 0.f) * w2.y;
#pragma unroll
    for (int o = 16; o > 0; o >>= 1) {
        s  += __shfl_xor_sync(0xffffffffu, s,  o);
        s2 += __shfl_xor_sync(0xffffffffu, s2, o);
    }

    if (lane == 0) {
        float comp = 1.f / (1.f + expf(-(s + bc2[0])));
        float tsc  = 1.f / (1.f + expf(-(s2 + bk2[0])));

        float lg[NE];
        float mx = -1e30f;
#pragma unroll
        for (int e = 0; e < NE; e++) { lg[e] = row[128 + e]; mx = fmaxf(mx, lg[e]); }
        float sum = 0.f;
#pragma unroll
        for (int e = 0; e < NE; e++) { lg[e] = expf(lg[e] - mx); sum += lg[e]; }
        float inv = 1.f / sum;
        float rw[NE];
#pragma unroll
        for (int e = 0; e < NE; e++) {
            rw[e] = lg[e] * inv;
            out[OUT_RW + (size_t)i * NE + e] = rw[e];
        }

        int   idx[4];
        float tv[4];
        bool  used[NE] = {false, false, false, false, false, false, false, false};
#pragma unroll
        for (int s4 = 0; s4 < 4; s4++) {
            int best = 0; float bv = -1e30f;
#pragma unroll
            for (int e = 0; e < NE; e++)
                if (!used[e] && rw[e] > bv) { bv = rw[e]; best = e; }
            used[best] = true; tv[s4] = bv; idx[s4] = best;
        }

        float combined = 0.7f * comp + 0.3f * tsc;
        int kk = (int)rintf(1.f + combined * 3.f);
        if (kk < 1) kk = 1; if (kk > 4) kk = 4;

        float ms = 0.f, mw[4];
#pragma unroll
        for (int s4 = 0; s4 < 4; s4++) { mw[s4] = (s4 < kk) ? tv[s4] : 0.f; ms += mw[s4]; }
        if (!(ms > 0.f)) ms = 1.f;
        float im = 1.f / ms;
#pragma unroll
        for (int s4 = 0; s4 < 4; s4++) {
            out[OUT_EW  + (size_t)i * 4 + s4] = mw[s4] * im;
            out[OUT_IDX + (size_t)i * 4 + s4] = (float)idx[s4];
        }
        out[OUT_C + i] = comp;

#pragma unroll
        for (int e = 0; e < NE; e++) atomicAdd(&sacc[e], (double)rw[e]);
        atomicAdd(&sacc[8], (double)comp * (double)comp);
    }
    __syncthreads();
    if (tid < 9) atomicAdd(&g_acc[tid], sacc[tid]);
}

// ============================================================== finalize
__global__ void finalize_kernel(float* __restrict__ out)
{
    double s = 0.0;
#pragma unroll
    for (int e = 0; e < NE; e++) {
        double u = g_acc[e] / (double)TOK - 1.0 / (double)NE;
        s += u * u;
    }
    out[OUT_LB] = (float)(s / (double)NE * 0.01);
    out[OUT_CR] = (float)(g_acc[8] / (double)TOK * 0.001);
}

// ============================================================== launch
extern "C" void kernel_launch(void* const* d_in, const int* in_sizes, int n_in,
                              void* d_out, int out_size)
{
    (void)in_sizes; (void)n_in; (void)out_size;
    const float* x    = (const float*)d_in[0];
    // d_in[1] = layer_idx (unused)
    const float* W_ih = (const float*)d_in[2];   // [768, 776]
    const float* W_hh = (const float*)d_in[3];   // [768, 256]
    const float* b_ih = (const float*)d_in[4];
    const float* b_hh = (const float*)d_in[5];
    const float* Wc1  = (const float*)d_in[6];
    const float* bc1  = (const float*)d_in[7];
    const float* Wc2  = (const float*)d_in[8];
    const float* bc2  = (const float*)d_in[9];
    const float* Wr   = (const float*)d_in[10];
    const float* br   = (const float*)d_in[11];
    const float* Wk1  = (const float*)d_in[12];
    const float* bk1  = (const float*)d_in[13];
    const float* Wk2  = (const float*)d_in[14];
    const float* bk2  = (const float*)d_in[15];
    float* out = (float*)d_out;

    static float* p_gi = nullptr;
    static float* p_g = nullptr;
    static float* p_feats = nullptr;
    static float* p_wc = nullptr;
    static float* p_bc = nullptr;
    if (!p_gi) {
        cudaGetSymbolAddress((void**)&p_gi,    g_gi);
        cudaGetSymbolAddress((void**)&p_g,     g_g);
        cudaGetSymbolAddress((void**)&p_feats, g_feats);
        cudaGetSymbolAddress((void**)&p_wc,    g_Wcomb);
        cudaGetSymbolAddress((void**)&p_bc,    g_bcomb);
    }

    // 1. pack head weights + zero loss accumulators
    prep_kernel<<<256, 256>>>(Wc1, bc1, Wr, br, Wk1, bk1);

    // 2. gi = x @ W_ih[:, :768]^T + b_ih   (M=65536, N=768, K=768)
    sgemm_nt<<<dim3(G3 / 128, TOK / 128), 256>>>(x, ND, W_ih, ND + NE, b_ih,
                                                 p_gi, G3, ND);

    // 3. GRU scan (one batch per 4-CTA cluster; st.async handshake)
    gru_kernel<<<dim3(4, NB), GRU_THREADS>>>(W_hh, b_hh, out + OUT_NH);

    // 4. heads: feats = g @ Wcomb^T + bcomb   (M=65536, N=256, K=256)
    sgemm_nt<<<dim3(256 / 128, TOK / 128), 256>>>(p_g, NH, p_wc, NH, p_bc,
                                                  p_feats, 256, NH);

    // 5. router epilogue
    router_kernel<<<TOK / 8, 256>>>(Wc2, bc2, Wk2, bk2, out);

    // 6. losses
    finalize_kernel<<<1, 1>>>(out);
}

// round 16
// speedup vs baseline: 1.4766x; 1.0018x over previous
#include <cuda_runtime.h>
#include <cstdint>
#include <math.h>

// ---------------------------------------------------------------- constants
#define NB   32
#define NS   2048
#define ND   768
#define NE   8
#define NH   256
#define TOK  (NB*NS)          // 65536
#define G3   (3*NH)           // 768

// output layout (float32, concatenated flattened tuple)
#define OUT_EW   0
#define OUT_IDX  (TOK*4)                // 262144
#define OUT_RW   (TOK*8)                // 524288
#define OUT_NH   (OUT_RW + TOK*8)       // 1048576
#define OUT_C    (OUT_NH + NB*NH)       // 1056768
#define OUT_LB   (OUT_C + TOK)          // 1122304
#define OUT_CR   (OUT_LB + 1)           // 1122305

// ---------------------------------------------------------------- scratch
__device__ float  g_gi[(size_t)TOK * G3];     // [B*S, 768]
__device__ float  g_g [(size_t)TOK * NH];     // [B*S, 256]
__device__ float  g_feats[(size_t)TOK * 256]; // heads gemm out
__device__ float  g_Wcomb[256 * 256];
__device__ float  g_bcomb[256];
__device__ double g_acc[9];                   // 8 usage sums + complexity^2 sum

// ---------------------------------------------------------------- helpers
__device__ __forceinline__ unsigned long long dup2f(float x) {
    unsigned long long r;
    asm("mov.b64 %0, {%1, %1};" : "=l"(r) : "f"(x));
    return r;
}
__device__ __forceinline__ void fma2(unsigned long long& acc,
                                     unsigned long long a, unsigned long long b) {
    asm("fma.rn.f32x2 %0, %1, %2, %0;" : "+l"(acc) : "l"(a), "l"(b));
}
__device__ __forceinline__ float2 unpack2(unsigned long long v) {
    float2 f;
    asm("mov.b64 {%0, %1}, %2;" : "=f"(f.x), "=f"(f.y) : "l"(v));
    return f;
}
__device__ __forceinline__ uint32_t smem_u32(const void* p) {
    uint32_t a;
    asm("{ .reg .u64 t; cvta.to.shared.u64 t, %1; cvt.u32.u64 %0, t; }"
        : "=r"(a) : "l"(p));
    return a;
}
__device__ __forceinline__ void cluster_arrive_() {
    asm volatile("barrier.cluster.arrive.aligned;" ::: "memory");
}
__device__ __forceinline__ void cluster_wait_() {
    asm volatile("barrier.cluster.wait.aligned;" ::: "memory");
}
__device__ __forceinline__ void cluster_sync_() {
    cluster_arrive_(); cluster_wait_();
}
// named-barrier split: producers arrive, consumers sync (total count matches)
__device__ __forceinline__ void bar_arrive_(uint32_t id, uint32_t cnt) {
    asm volatile("bar.arrive %0, %1;" :: "r"(id), "r"(cnt) : "memory");
}
__device__ __forceinline__ void bar_sync_(uint32_t id, uint32_t cnt) {
    asm volatile("bar.sync %0, %1;" :: "r"(id), "r"(cnt) : "memory");
}
// fast gate math: MUFU-based (round-11 proven)
__device__ __forceinline__ float fast_sigmoid(float x) {
    return __fdividef(1.f, 1.f + __expf(-x));
}
__device__ __forceinline__ float fast_tanh(float x) {
    return 1.f - __fdividef(2.f, __expf(2.f * x) + 1.f);
}
// st.async: data store carries mbarrier tx-completion (no arrive storm).
__device__ __forceinline__ void st_async_f32(uint32_t addr, uint32_t mbar,
                                             uint32_t rank, float v) {
    asm volatile(
        "{\n\t.reg .b32 ra, rb;\n\t"
        "mapa.shared::cluster.u32 ra, %0, %2;\n\t"
        "mapa.shared::cluster.u32 rb, %1, %2;\n\t"
        "st.async.weak.shared::cluster.mbarrier::complete_tx::bytes.b32 [ra], %3, [rb];\n\t"
        "}" :: "r"(addr), "r"(mbar), "r"(rank), "f"(v) : "memory");
}
__device__ __forceinline__ void mbar_arrive_expect_tx(uint32_t mbar, uint32_t bytes) {
    asm volatile("mbarrier.arrive.expect_tx.shared.b64 _, [%0], %1;"
                 :: "r"(mbar), "r"(bytes) : "memory");
}
__device__ __forceinline__ void mbar_wait_(uint32_t addr, uint32_t parity) {
    uint32_t done;
    asm volatile(
        "{\n\t.reg .pred p;\n\t"
        "mbarrier.try_wait.parity.acquire.cluster.shared::cta.b64 p, [%1], %2;\n\t"
        "selp.b32 %0, 1, 0, p;\n\t}"
        : "=r"(done) : "r"(addr), "r"(parity) : "memory");
    if (!done) {
        asm volatile(
            "{\n\t.reg .pred P1;\n\t"
            "WAITLP_%=:\n\t"
            "mbarrier.try_wait.parity.acquire.cluster.shared::cta.b64 P1, [%0], %1, 0x989680;\n\t"
            "@!P1 bra WAITLP_%=;\n\t"
            "}" :: "r"(addr), "r"(parity) : "memory");
    }
}

// ============================================================== SGEMM (NT)
// Round-14 proven: double-buffered, one __syncthreads per BK=16 tile.
__global__ __launch_bounds__(256, 2)
void sgemm_nt(const float* __restrict__ A, int lda,
              const float* __restrict__ B, int ldb,
              const float* __restrict__ bias,
              float* __restrict__ C, int ldc, int K)
{
    __shared__ float As[2][16 * 128];
    __shared__ float Bs[2][16 * 128];

    const int tid = threadIdx.x;
    const int tx  = tid & 15, ty = tid >> 4;
    const int tx4 = tx * 4,  ty4 = ty * 4;
    const size_t bm = (size_t)blockIdx.y * 128;
    const size_t bn = (size_t)blockIdx.x * 128;

    const int r0 = tid >> 2;          // 0..63
    const int r1 = r0 + 64;
    const int c4 = (tid & 3) * 4;     // 0,4,8,12

    const float* Ag0 = A + (bm + r0) * (size_t)lda + c4;
    const float* Ag1 = A + (bm + r1) * (size_t)lda + c4;
    const float* Bg0 = B + (bn + r0) * (size_t)ldb + c4;
    const float* Bg1 = B + (bn + r1) * (size_t)ldb + c4;

    unsigned long long acc[8][4];
#pragma unroll
    for (int i = 0; i < 8; i++)
#pragma unroll
        for (int jp = 0; jp < 4; jp++) acc[i][jp] = 0ull;

    float4 pa0 = *(const float4*)Ag0;
    float4 pa1 = *(const float4*)Ag1;
    float4 pb0 = *(const float4*)Bg0;
    float4 pb1 = *(const float4*)Bg1;
#pragma unroll
    for (int jj = 0; jj < 4; jj++) {
        As[0][(c4 + jj) * 128 + r0] = ((const float*)&pa0)[jj];
        As[0][(c4 + jj) * 128 + r1] = ((const float*)&pa1)[jj];
        Bs[0][(c4 + jj) * 128 + r0] = ((const float*)&pb0)[jj];
        Bs[0][(c4 + jj) * 128 + r1] = ((const float*)&pb1)[jj];
    }
    __syncthreads();

    const int nk = K >> 4;
    int p = 0;
    for (int kt = 0; kt < nk; kt++) {
        const bool has_next = (kt + 1 < nk);
        if (has_next) {
            const int off = (kt + 1) * 16;
            pa0 = *(const float4*)(Ag0 + off);
            pa1 = *(const float4*)(Ag1 + off);
            pb0 = *(const float4*)(Bg0 + off);
            pb1 = *(const float4*)(Bg1 + off);
        }

        const float* asb = As[p];
        const float* bsb = Bs[p];
#pragma unroll
        for (int k = 0; k < 16; k++) {
            const float* asr = asb + k * 128;
            float4 a0 = *(const float4*)(asr + ty4);
            float4 a1 = *(const float4*)(asr + 64 + ty4);
            const ulonglong2* bsr = (const ulonglong2*)(bsb + k * 128);
            ulonglong2 b0 = bsr[tx];
            ulonglong2 b1 = bsr[16 + tx];
            float am[8] = {a0.x, a0.y, a0.z, a0.w, a1.x, a1.y, a1.z, a1.w};
#pragma unroll
            for (int i = 0; i < 8; i++) {
                unsigned long long ad = dup2f(am[i]);
                fma2(acc[i][0], ad, b0.x);
                fma2(acc[i][1], ad, b0.y);
                fma2(acc[i][2], ad, b1.x);
                fma2(acc[i][3], ad, b1.y);
            }
        }

        if (has_next) {
            float* ad_ = As[p ^ 1];
            float* bd_ = Bs[p ^ 1];
#pragma unroll
            for (int jj = 0; jj < 4; jj++) {
                ad_[(c4 + jj) * 128 + r0] = ((const float*)&pa0)[jj];
                ad_[(c4 + jj) * 128 + r1] = ((const float*)&pa1)[jj];
                bd_[(c4 + jj) * 128 + r0] = ((const float*)&pb0)[jj];
                bd_[(c4 + jj) * 128 + r1] = ((const float*)&pb1)[jj];
            }
        }
        __syncthreads();
        p ^= 1;
    }

    float4 bb0 = *(const float4*)(bias + bn + tx4);
    float4 bb1 = *(const float4*)(bias + bn + 64 + tx4);

#pragma unroll
    for (int i = 0; i < 8; i++) {
        size_t m = bm + (size_t)((i < 4) ? (ty4 + i) : (64 + ty4 + (i - 4)));
        float2 p0 = unpack2(acc[i][0]);
        float2 p1 = unpack2(acc[i][1]);
        float2 p2 = unpack2(acc[i][2]);
        float2 p3 = unpack2(acc[i][3]);
        float4 o0 = make_float4(p0.x + bb0.x, p0.y + bb0.y, p1.x + bb0.z, p1.y + bb0.w);
        float4 o1 = make_float4(p2.x + bb1.x, p2.y + bb1.y, p3.x + bb1.z, p3.y + bb1.w);
        *(float4*)&C[m * (size_t)ldc + bn + tx4]      = o0;
        *(float4*)&C[m * (size_t)ldc + bn + 64 + tx4] = o1;
    }
}

// ============================================================== GRU scan
// Round-15 st.async handshake + this round's critical-path cuts:
//  - named-barrier producer/consumer split: warps 2-11 bar.arrive(1) and go
//    straight to the mbarrier wait (pre-parked for wakeup); gate warps 0-1
//    bar.sync(1). Safety: ps overwrite at t+1 requires passing mbar-wait(t),
//    which requires own-CTA gate stores, which follow the gates' ps reads.
//  - gate thread uses its OWN gemv partial (it produced ps[tid]) instead of
//    re-loading it -> one dependent LDS off the gate-chain head.
//  - expect_tx posted by warp 11 (off the gate warps).
#define GRU_THREADS 384

__global__ void __cluster_dims__(4, 1, 1) __launch_bounds__(GRU_THREADS, 1)
gru_kernel(const float* __restrict__ W_hh, const float* __restrict__ b_hh,
           float* __restrict__ out_hidden)
{
    __shared__ float hb[2][256];            // double-buffered hidden state
    __shared__ float ps[GRU_THREADS];       // partial sums (half0 | half1)
    __shared__ __align__(8) unsigned long long bar[2];

    const int tid  = threadIdx.x;
    const int rank = blockIdx.x;            // 0..3
    const int b    = blockIdx.y;            // 0..31
    const int half = (tid >= 192) ? 1 : 0;  // K-half (warp-uniform)
    const int r    = tid - half * 192;      // row 0..191  (= g*64 + j)
    const int g    = r >> 6;
    const int j    = r & 63;
    const int u    = rank * 64 + tid;       // unit id (valid only for tid<64)
    const bool is_gate_warp = (tid < 64);   // warps 0,1 (uniform per warp)

    ulonglong2 w[32];
    {
        const ulonglong2* src = (const ulonglong2*)
            (W_hh + ((size_t)(g * 256 + rank * 64 + j)) * 256 + half * 128);
#pragma unroll
        for (int i = 0; i < 32; i++) w[i] = src[i];
    }

    if (tid < 256) { hb[0][tid] = 0.f; hb[1][tid] = 0.f; }

    const uint32_t bar0 = smem_u32(&bar[0]);
    const uint32_t bar1 = smem_u32(&bar[1]);
    if (tid == 0) {
        asm volatile("mbarrier.init.shared.b64 [%0], 1;" :: "r"(bar0) : "memory");
        asm volatile("mbarrier.init.shared.b64 [%0], 1;" :: "r"(bar1) : "memory");
    }

    float bhr = 0.f, bhz = 0.f, bhn = 0.f;
    if (tid < 64) {
        bhr = b_hh[u]; bhz = b_hh[256 + u]; bhn = b_hh[512 + u];
    }
    __syncthreads();
    cluster_sync_();   // all CTAs' barriers initialized before any remote store

    const float* gi_base = g_gi + (size_t)b * NS * G3;
    float*       gout    = g_g  + (size_t)b * NS * NH;
    const uint32_t hb_u32 = smem_u32(&hb[0][0]);

    float cr = 0.f, cz = 0.f, cn = 0.f;
    if (tid < 64) { cr = gi_base[u]; cz = gi_base[256 + u]; cn = gi_base[512 + u]; }

    int p = 0;
#pragma unroll 1
    for (int t = 0; t < NS; t++) {
        const uint32_t barx = (t & 1) ? bar1 : bar0;
        // expect posted by a NON-gate warp (warp 11 lane 0)
        if (tid == 352) mbar_arrive_expect_tx(barx, 1024);

        // prefetch gi(t+1)
        float nr = 0.f, nz = 0.f, nn = 0.f;
        if (tid < 64 && t + 1 < NS) {
            const float* gn_ = gi_base + (size_t)(t + 1) * G3;
            nr = gn_[u]; nz = gn_[256 + u]; nn = gn_[512 + u];
        }

        // gemv: 128-MAC partial dot from register W, broadcast-LDS h
        const ulonglong2* hv = (const ulonglong2*)(&hb[p][half * 128]);
        unsigned long long a0 = 0ull, a1 = 0ull, a2 = 0ull, a3 = 0ull;
#pragma unroll
        for (int i = 0; i < 32; i += 2) {
            ulonglong2 h0 = hv[i], h1 = hv[i + 1];
            fma2(a0, w[i].x,     h0.x);
            fma2(a1, w[i].y,     h0.y);
            fma2(a2, w[i + 1].x, h1.x);
            fma2(a3, w[i + 1].y, h1.y);
        }
        float2 f0 = unpack2(a0), f1 = unpack2(a1), f2 = unpack2(a2), f3 = unpack2(a3);
        const float mydot = ((f0.x + f0.y) + (f1.x + f1.y)) +
                            ((f2.x + f2.y) + (f3.x + f3.y));
        ps[tid] = mydot;

        if (!is_gate_warp) {
            // producers: arrive and park at the mbarrier immediately
            bar_arrive_(1, GRU_THREADS);
            mbar_wait_(barx, (uint32_t)((t >> 1) & 1));
        } else {
            bar_sync_(1, GRU_THREADS);   // wait for all 384 ps partials

            float hold = hb[p][u];
            // own partial IS ps[tid] (r-gate, half 0) — skip that LDS
            float hr = mydot         + ps[192 + tid];
            float hz = ps[64 + tid]  + ps[256 + tid];
            float hn = ps[128 + tid] + ps[320 + tid];
            float rr = fast_sigmoid(cr + bhr + hr);
            float zz = fast_sigmoid(cz + bhz + hz);
            float n2 = fast_tanh(cn + bhn + rr * hn);
            float hnew = (1.f - zz) * n2 + zz * hold;

            // h(t+1) to all 4 CTAs; each store signals 4 tx bytes
            uint32_t dst = hb_u32 + (uint32_t)((((p ^ 1) * 256) + u) * 4);
#pragma unroll
            for (int c = 0; c < 4; c++)
                st_async_f32(dst, barx, (uint32_t)c, hnew);

            // global writes in the wait shadow
            gout[(size_t)t * NH + u] = hnew;
            if (t == NS - 1) out_hidden[b * NH + u] = hnew;

            mbar_wait_(barx, (uint32_t)((t >> 1) & 1));
        }
        p ^= 1;
        cr = nr; cz = nz; cn = nn;
    }
    // no CTA exits while peers may still st.async into its smem
    cluster_sync_();
}

// ============================================================== prep
__global__ void prep_kernel(const float* __restrict__ Wc1, const float* __restrict__ bc1,
                            const float* __restrict__ Wr,  const float* __restrict__ br,
                            const float* __restrict__ Wk1, const float* __restrict__ bk1)
{
    int r = blockIdx.x, c = threadIdx.x;
    float v = 0.f, bv = 0.f;
    if (r < 128)       { v = Wc1[r * 256 + c];         bv = bc1[r];       }
    else if (r < 136)  { v = Wr [(r - 128) * 256 + c]; bv = br [r - 128]; }
    else if (r < 200)  { v = Wk1[(r - 136) * 256 + c]; bv = bk1[r - 136]; }
    g_Wcomb[r * 256 + c] = v;
    if (c == 0) g_bcomb[r] = bv;
    if (r == 0 && c < 9) g_acc[c] = 0.0;
}

// ============================================================== router
__global__ __launch_bounds__(256)
void router_kernel(const float* __restrict__ Wc2, const float* __restrict__ bc2,
                   const float* __restrict__ Wk2, const float* __restrict__ bk2,
                   float* __restrict__ out)
{
    __shared__ double sacc[9];
    const int tid = threadIdx.x;
    if (tid < 9) sacc[tid] = 0.0;
    __syncthreads();

    const int warp = tid >> 5, lane = tid & 31;
    const int i = blockIdx.x * 8 + warp;
    const float* row = g_feats + (size_t)i * 256;

    float4 f = *(const float4*)(row + lane * 4);
    float4 w = *(const float4*)(Wc2 + lane * 4);
    float s = fmaxf(f.x, 0.f) * w.x + fmaxf(f.y, 0.f) * w.y +
              fmaxf(f.z, 0.f) * w.z + fmaxf(f.w, 0.f) * w.w;
    float2 f2 = *(const float2*)(row + 136 + lane * 2);
    float2 w2 = *(const float2*)(Wk2 + lane * 2);
    float s2 = fmaxf(f2.x, 0.f) * w2.x + fmaxf(f2.y, 0.f) * w2.y;
#pragma unroll
    for (int o = 16; o > 0; o >>= 1) {
        s  += __shfl_xor_sync(0xffffffffu, s,  o);
        s2 += __shfl_xor_sync(0xffffffffu, s2, o);
    }

    if (lane == 0) {
        float comp = 1.f / (1.f + expf(-(s + bc2[0])));
        float tsc  = 1.f / (1.f + expf(-(s2 + bk2[0])));

        float lg[NE];
        float mx = -1e30f;
#pragma unroll
        for (int e = 0; e < NE; e++) { lg[e] = row[128 + e]; mx = fmaxf(mx, lg[e]); }
        float sum = 0.f;
#pragma unroll
        for (int e = 0; e < NE; e++) { lg[e] = expf(lg[e] - mx); sum += lg[e]; }
        float inv = 1.f / sum;
        float rw[NE];
#pragma unroll
        for (int e = 0; e < NE; e++) {
            rw[e] = lg[e] * inv;
            out[OUT_RW + (size_t)i * NE + e] = rw[e];
        }

        int   idx[4];
        float tv[4];
        bool  used[NE] = {false, false, false, false, false, false, false, false};
#pragma unroll
        for (int s4 = 0; s4 < 4; s4++) {
            int best = 0; float bv = -1e30f;
#pragma unroll
            for (int e = 0; e < NE; e++)
                if (!used[e] && rw[e] > bv) { bv = rw[e]; best = e; }
            used[best] = true; tv[s4] = bv; idx[s4] = best;
        }

        float combined = 0.7f * comp + 0.3f * tsc;
        int kk = (int)rintf(1.f + combined * 3.f);
        if (kk < 1) kk = 1; if (kk > 4) kk = 4;

        float ms = 0.f, mw[4];
#pragma unroll
        for (int s4 = 0; s4 < 4; s4++) { mw[s4] = (s4 < kk) ? tv[s4] : 0.f; ms += mw[s4]; }
        if (!(ms > 0.f)) ms = 1.f;
        float im = 1.f / ms;
#pragma unroll
        for (int s4 = 0; s4 < 4; s4++) {
            out[OUT_EW  + (size_t)i * 4 + s4] = mw[s4] * im;
            out[OUT_IDX + (size_t)i * 4 + s4] = (float)idx[s4];
        }
        out[OUT_C + i] = comp;

#pragma unroll
        for (int e = 0; e < NE; e++) atomicAdd(&sacc[e], (double)rw[e]);
        atomicAdd(&sacc[8], (double)comp * (double)comp);
    }
    __syncthreads();
    if (tid < 9) atomicAdd(&g_acc[tid], sacc[tid]);
}

// ============================================================== finalize
__global__ void finalize_kernel(float* __restrict__ out)
{
    double s = 0.0;
#pragma unroll
    for (int e = 0; e < NE; e++) {
        double u = g_acc[e] / (double)TOK - 1.0 / (double)NE;
        s += u * u;
    }
    out[OUT_LB] = (float)(s / (double)NE * 0.01);
    out[OUT_CR] = (float)(g_acc[8] / (double)TOK * 0.001);
}

// ============================================================== launch
extern "C" void kernel_launch(void* const* d_in, const int* in_sizes, int n_in,
                              void* d_out, int out_size)
{
    (void)in_sizes; (void)n_in; (void)out_size;
    const float* x    = (const float*)d_in[0];
    // d_in[1] = layer_idx (unused)
    const float* W_ih = (const float*)d_in[2];   // [768, 776]
    const float* W_hh = (const float*)d_in[3];   // [768, 256]
    const float* b_ih = (const float*)d_in[4];
    const float* b_hh = (const float*)d_in[5];
    const float* Wc1  = (const float*)d_in[6];
    const float* bc1  = (const float*)d_in[7];
    const float* Wc2  = (const float*)d_in[8];
    const float* bc2  = (const float*)d_in[9];
    const float* Wr   = (const float*)d_in[10];
    const float* br   = (const float*)d_in[11];
    const float* Wk1  = (const float*)d_in[12];
    const float* bk1  = (const float*)d_in[13];
    const float* Wk2  = (const float*)d_in[14];
    const float* bk2  = (const float*)d_in[15];
    float* out = (float*)d_out;

    static float* p_gi = nullptr;
    static float* p_g = nullptr;
    static float* p_feats = nullptr;
    static float* p_wc = nullptr;
    static float* p_bc = nullptr;
    if (!p_gi) {
        cudaGetSymbolAddress((void**)&p_gi,    g_gi);
        cudaGetSymbolAddress((void**)&p_g,     g_g);
        cudaGetSymbolAddress((void**)&p_feats, g_feats);
        cudaGetSymbolAddress((void**)&p_wc,    g_Wcomb);
        cudaGetSymbolAddress((void**)&p_bc,    g_bcomb);
    }

    // 1. pack head weights + zero loss accumulators
    prep_kernel<<<256, 256>>>(Wc1, bc1, Wr, br, Wk1, bk1);

    // 2. gi = x @ W_ih[:, :768]^T + b_ih   (M=65536, N=768, K=768)
    sgemm_nt<<<dim3(G3 / 128, TOK / 128), 256>>>(x, ND, W_ih, ND + NE, b_ih,
                                                 p_gi, G3, ND);

    // 3. GRU scan (one batch per 4-CTA cluster; st.async handshake)
    gru_kernel<<<dim3(4, NB), GRU_THREADS>>>(W_hh, b_hh, out + OUT_NH);

    // 4. heads: feats = g @ Wcomb^T + bcomb   (M=65536, N=256, K=256)
    sgemm_nt<<<dim3(256 / 128, TOK / 128), 256>>>(p_g, NH, p_wc, NH, p_bc,
                                                  p_feats, 256, NH);

    // 5. router epilogue
    router_kernel<<<TOK / 8, 256>>>(Wc2, bc2, Wk2, bk2, out);

    // 6. losses
    finalize_kernel<<<1, 1>>>(out);
}